// round 11
// baseline (speedup 1.0000x reference)
#include <cstdint>
#include <cuda_runtime.h>
#include <cuda_fp16.h>
#include <cuda_bf16.h>

#define NN 100000
#define EE 1600000
#define IN_F 256
#define HH 4
#define CC 32
#define HC 128           // HH*CC
#define AST 40           // smem stride in half (80B rows: conflict-free ldmatrix)

// ---------------- device scratch (no allocations allowed) ----------------
__device__ __half g_feat_h[NN * HC];  // projected features [N, H*C] (fp16)
__device__ float g_el[NN * HH];       // left attention logits  [N,H]
__device__ float g_er[NN * HH];       // right attention logits [N,H]
__device__ int   g_deg[NN];           // in-degree histogram
__device__ int   g_rowoff[NN + 1];    // CSR row offsets (by dst)
__device__ int   g_cursor[NN];        // scatter cursors
__device__ int   g_srcsorted[EE];     // src node id per edge, grouped by dst
__device__ __half g_Wt[HC * IN_F];    // W^T fp16: [n=128][k=256]

// ---------------- kernel 0: W -> W^T fp16 ----------------
__global__ void wprep_kernel(const float* __restrict__ W) {
    int i = blockIdx.x * blockDim.x + threadIdx.x;  // over 256*128
    if (i >= IN_F * HC) return;
    int k = i >> 7, n = i & 127;
    g_Wt[n * IN_F + k] = __float2half_rn(W[i]);
}

// ---------------- kernel 1: feat = x @ W via fp16 tensor cores ----------
// Block: 128x128 out tile, 256 thr = 8 warps as 4(m) x 2(n); warp tile 32x64.
// Fused epilogue computes el/er per (row, head) via quad-shfl reduction.
__global__ __launch_bounds__(256) void gemm_feat_tc_kernel(
    const float* __restrict__ x,
    const float* __restrict__ attn_l, const float* __restrict__ attn_r)
{
    __shared__ __half As[128][AST];
    __shared__ __half Bs[128][AST];

    int tid = threadIdx.x, lane = tid & 31, wid = tid >> 5;
    int warp_m = wid >> 1;          // 0..3
    int warp_n = wid & 1;           // 0..1
    int row0 = blockIdx.x * 128;

    float acc[2][8][4];
#pragma unroll
    for (int im = 0; im < 2; im++)
#pragma unroll
        for (int jn = 0; jn < 8; jn++)
#pragma unroll
            for (int r = 0; r < 4; r++) acc[im][jn][r] = 0.f;

    for (int k0 = 0; k0 < IN_F; k0 += 32) {
        // x tile: 128 rows x 32 k, fp32 -> fp16
#pragma unroll
        for (int l = 0; l < 4; l++) {
            int idx = tid + l * 256;            // 0..1023 float4 slots
            int r = idx >> 3, c4 = (idx & 7) << 2;
            int row = row0 + r;
            float4 v = make_float4(0.f, 0.f, 0.f, 0.f);
            if (row < NN)
                v = *reinterpret_cast<const float4*>(&x[(size_t)row * IN_F + k0 + c4]);
            *reinterpret_cast<__half2*>(&As[r][c4])     = __floats2half2_rn(v.x, v.y);
            *reinterpret_cast<__half2*>(&As[r][c4 + 2]) = __floats2half2_rn(v.z, v.w);
        }
        // W tile: [128 n][32 k] fp16, preconverted
        {
            int idx8 = tid;                     // 0..255, need 512 uint4 slots => 2 per thread
#pragma unroll
            for (int l = 0; l < 2; l++) {
                int s = idx8 + l * 256;
                int n = s >> 2, k8 = (s & 3) << 3;
                *reinterpret_cast<uint4*>(&Bs[n][k8]) =
                    *reinterpret_cast<const uint4*>(&g_Wt[n * IN_F + k0 + k8]);
            }
        }
        __syncthreads();

#pragma unroll
        for (int kk = 0; kk < 32; kk += 16) {
            uint32_t af[2][4];
#pragma unroll
            for (int im = 0; im < 2; im++) {
                uint32_t adr = (uint32_t)__cvta_generic_to_shared(
                    &As[warp_m * 32 + im * 16 + (lane & 15)][kk + ((lane >> 4) << 3)]);
                asm volatile("ldmatrix.sync.aligned.m8n8.x4.shared.b16 {%0,%1,%2,%3}, [%4];"
                             : "=r"(af[im][0]), "=r"(af[im][1]), "=r"(af[im][2]), "=r"(af[im][3])
                             : "r"(adr));
            }
#pragma unroll
            for (int jn = 0; jn < 8; jn++) {
                int nb = warp_n * 64 + jn * 8;
                uint32_t bf[2];
                uint32_t adr_b = (uint32_t)__cvta_generic_to_shared(
                    &Bs[nb + (lane & 7)][kk + (((lane >> 3) & 1) << 3)]);
                asm volatile("ldmatrix.sync.aligned.m8n8.x2.shared.b16 {%0,%1}, [%2];"
                             : "=r"(bf[0]), "=r"(bf[1]) : "r"(adr_b));
#pragma unroll
                for (int im = 0; im < 2; im++) {
                    float* c = acc[im][jn];
                    asm volatile(
                        "mma.sync.aligned.m16n8k16.row.col.f32.f16.f16.f32 "
                        "{%0,%1,%2,%3}, {%4,%5,%6,%7}, {%8,%9}, {%0,%1,%2,%3};"
                        : "+f"(c[0]), "+f"(c[1]), "+f"(c[2]), "+f"(c[3])
                        : "r"(af[im][0]), "r"(af[im][1]), "r"(af[im][2]), "r"(af[im][3]),
                          "r"(bf[0]), "r"(bf[1]));
                }
            }
        }
        __syncthreads();
    }

    // ---- epilogue: store feat (fp16), compute el/er per (row, head) ----
    int quad = lane >> 2, tc = lane & 3;
    float pel[2][2][2], per[2][2][2];   // [im][rowhalf][headhalf]
#pragma unroll
    for (int im = 0; im < 2; im++)
#pragma unroll
        for (int rh = 0; rh < 2; rh++)
#pragma unroll
            for (int hh = 0; hh < 2; hh++) { pel[im][rh][hh] = 0.f; per[im][rh][hh] = 0.f; }

#pragma unroll
    for (int im = 0; im < 2; im++) {
        int rowA = row0 + warp_m * 32 + im * 16 + quad;
#pragma unroll
        for (int jn = 0; jn < 8; jn++) {
            int col = warp_n * 64 + jn * 8 + tc * 2;
            int hh = jn >> 2;
            float* c = acc[im][jn];
            float a0 = attn_l[col], a1 = attn_l[col + 1];
            float b0 = attn_r[col], b1 = attn_r[col + 1];
            pel[im][0][hh] += c[0] * a0 + c[1] * a1;
            per[im][0][hh] += c[0] * b0 + c[1] * b1;
            pel[im][1][hh] += c[2] * a0 + c[3] * a1;
            per[im][1][hh] += c[2] * b0 + c[3] * b1;
            if (rowA < NN)
                *reinterpret_cast<__half2*>(&g_feat_h[(size_t)rowA * HC + col]) =
                    __floats2half2_rn(c[0], c[1]);
            if (rowA + 8 < NN)
                *reinterpret_cast<__half2*>(&g_feat_h[(size_t)(rowA + 8) * HC + col]) =
                    __floats2half2_rn(c[2], c[3]);
        }
    }
#pragma unroll
    for (int im = 0; im < 2; im++)
#pragma unroll
        for (int rh = 0; rh < 2; rh++)
#pragma unroll
            for (int hh = 0; hh < 2; hh++) {
                float e = pel[im][rh][hh], r = per[im][rh][hh];
                e += __shfl_xor_sync(0xffffffffu, e, 1);
                e += __shfl_xor_sync(0xffffffffu, e, 2);
                r += __shfl_xor_sync(0xffffffffu, r, 1);
                r += __shfl_xor_sync(0xffffffffu, r, 2);
                if (tc == 0) {
                    int row = row0 + warp_m * 32 + im * 16 + quad + rh * 8;
                    int head = warp_n * 2 + hh;
                    if (row < NN) {
                        g_el[row * HH + head] = e;
                        g_er[row * HH + head] = r;
                    }
                }
            }
}

// ---------------- CSR build ----------------
__global__ void zero_deg_kernel() {
    int i = blockIdx.x * blockDim.x + threadIdx.x;
    if (i < NN) g_deg[i] = 0;
}

__global__ void histo_kernel(const int* __restrict__ dst) {
    int e = blockIdx.x * blockDim.x + threadIdx.x;
    if (e < EE) atomicAdd(&g_deg[dst[e]], 1);
}

// single-block exclusive scan of g_deg -> g_rowoff/g_cursor (warp-shfl based)
__global__ __launch_bounds__(1024) void scan_all_kernel() {
    __shared__ int warpsums[32];
    __shared__ int s_carry;
    int lane = threadIdx.x & 31, wd = threadIdx.x >> 5;
    if (threadIdx.x == 0) s_carry = 0;
    __syncthreads();
    for (int base = 0; base < NN; base += 1024) {
        int i = base + threadIdx.x;
        int v = (i < NN) ? g_deg[i] : 0;
        int sc = v;                               // inclusive warp scan
#pragma unroll
        for (int off = 1; off < 32; off <<= 1) {
            int t = __shfl_up_sync(0xffffffffu, sc, off);
            if (lane >= off) sc += t;
        }
        if (lane == 31) warpsums[wd] = sc;
        __syncthreads();
        if (wd == 0) {
            int ws = warpsums[lane];
#pragma unroll
            for (int off = 1; off < 32; off <<= 1) {
                int t = __shfl_up_sync(0xffffffffu, ws, off);
                if (lane >= off) ws += t;
            }
            warpsums[lane] = ws;                  // inclusive scan of warp totals
        }
        __syncthreads();
        int carry = s_carry;
        int woff = (wd > 0) ? warpsums[wd - 1] : 0;
        int excl = carry + woff + sc - v;
        if (i < NN) { g_rowoff[i] = excl; g_cursor[i] = excl; }
        __syncthreads();                          // everyone read s_carry
        if (threadIdx.x == 0) s_carry = carry + warpsums[31];
        __syncthreads();
    }
    if (threadIdx.x == 0) g_rowoff[NN] = EE;
}

__global__ void scatter_kernel(const int* __restrict__ src,
                               const int* __restrict__ dst) {
    int e = blockIdx.x * blockDim.x + threadIdx.x;
    if (e >= EE) return;
    int pos = atomicAdd(&g_cursor[dst[e]], 1);
    g_srcsorted[pos] = src[e];
}

// ------- fused single-pass softmax-aggregate + head-mean + relu -------
__global__ __launch_bounds__(256) void aggregate_fused_kernel(
    const float* __restrict__ bias, float* __restrict__ out)
{
    __shared__ float sh_ex[8][32][4];   // [warp][edge-in-chunk][head]
    int wslot = threadIdx.x >> 5;
    int warp = (blockIdx.x * blockDim.x + threadIdx.x) >> 5;
    int lane = threadIdx.x & 31;
    if (warp >= NN) return;
    int n = warp;
    int head = lane >> 3;

    int start = g_rowoff[n];
    int end   = g_rowoff[n + 1];

    float4 er4 = *reinterpret_cast<const float4*>(&g_er[n * HH]);

    float4 den = make_float4(0.f, 0.f, 0.f, 0.f);
    float4 acc = make_float4(0.f, 0.f, 0.f, 0.f);
    const uint2* feat2 = reinterpret_cast<const uint2*>(g_feat_h);

    for (int j0 = start; j0 < end; j0 += 32) {
        int jj = j0 + lane;
        int sj = 0;
        float4 ex4 = make_float4(0.f, 0.f, 0.f, 0.f);
        if (jj < end) {
            sj = g_srcsorted[jj];
            float4 el4 = *reinterpret_cast<const float4*>(&g_el[sj * HH]);
            float v0 = el4.x + er4.x, v1 = el4.y + er4.y;
            float v2 = el4.z + er4.z, v3 = el4.w + er4.w;
            v0 = v0 > 0.f ? v0 : 0.2f * v0;
            v1 = v1 > 0.f ? v1 : 0.2f * v1;
            v2 = v2 > 0.f ? v2 : 0.2f * v2;
            v3 = v3 > 0.f ? v3 : 0.2f * v3;
            ex4 = make_float4(__expf(v0), __expf(v1), __expf(v2), __expf(v3));
            den.x += ex4.x; den.y += ex4.y; den.z += ex4.z; den.w += ex4.w;
        }
        *reinterpret_cast<float4*>(&sh_ex[wslot][lane][0]) = ex4;
        __syncwarp();
        int m = end - j0; if (m > 32) m = 32;
        for (int t = 0; t < m; t++) {
            int s = __shfl_sync(0xffffffffu, sj, t);
            float num = sh_ex[wslot][t][head];          // broadcast LDS
            uint2 u = feat2[(size_t)s * 32 + lane];     // 8B fp16 gather
            float2 f01 = __half22float2(*reinterpret_cast<__half2*>(&u.x));
            float2 f23 = __half22float2(*reinterpret_cast<__half2*>(&u.y));
            acc.x += num * f01.x; acc.y += num * f01.y;
            acc.z += num * f23.x; acc.w += num * f23.y;
        }
        __syncwarp();
    }

#pragma unroll
    for (int off = 16; off > 0; off >>= 1) {
        den.x += __shfl_xor_sync(0xffffffffu, den.x, off);
        den.y += __shfl_xor_sync(0xffffffffu, den.y, off);
        den.z += __shfl_xor_sync(0xffffffffu, den.z, off);
        den.w += __shfl_xor_sync(0xffffffffu, den.w, off);
    }
    float dmine = (head == 0) ? den.x : (head == 1) ? den.y
                 : (head == 2) ? den.z : den.w;
    float rinv = (dmine > 0.f) ? __fdividef(1.f, dmine) : 0.f;
    acc.x *= rinv; acc.y *= rinv; acc.z *= rinv; acc.w *= rinv;

#pragma unroll
    for (int off = 8; off <= 16; off <<= 1) {
        acc.x += __shfl_xor_sync(0xffffffffu, acc.x, off);
        acc.y += __shfl_xor_sync(0xffffffffu, acc.y, off);
        acc.z += __shfl_xor_sync(0xffffffffu, acc.z, off);
        acc.w += __shfl_xor_sync(0xffffffffu, acc.w, off);
    }
    if (lane < 8) {
        float bs[4] = {0.f, 0.f, 0.f, 0.f};
#pragma unroll
        for (int h = 0; h < HH; h++) {
#pragma unroll
            for (int k = 0; k < 4; k++) bs[k] += bias[h * CC + lane * 4 + k];
        }
        float4 o;
        o.x = fmaxf(0.25f * (acc.x + bs[0]), 0.f);
        o.y = fmaxf(0.25f * (acc.y + bs[1]), 0.f);
        o.z = fmaxf(0.25f * (acc.z + bs[2]), 0.f);
        o.w = fmaxf(0.25f * (acc.w + bs[3]), 0.f);
        reinterpret_cast<float4*>(out)[n * 8 + lane] = o;
    }
}

// ---------------- launch: CSR build forked onto side stream ----------------
extern "C" void kernel_launch(void* const* d_in, const int* in_sizes, int n_in,
                              void* d_out, int out_size)
{
    const float* x      = (const float*)d_in[0];
    const int*   src    = (const int*)d_in[1];
    const int*   dst    = (const int*)d_in[2];
    const float* W      = (const float*)d_in[3];
    const float* attn_l = (const float*)d_in[4];
    const float* attn_r = (const float*)d_in[5];
    const float* bias   = (const float*)d_in[6];
    float* out = (float*)d_out;

    static cudaStream_t s2 = nullptr;
    static cudaEvent_t evFork = nullptr, evJoin = nullptr;
    static bool ok2 = false;
    if (!evFork) {
        ok2 = (cudaStreamCreateWithFlags(&s2, cudaStreamNonBlocking) == cudaSuccess);
        cudaEventCreateWithFlags(&evFork, cudaEventDisableTiming);
        cudaEventCreateWithFlags(&evJoin, cudaEventDisableTiming);
    }
    cudaStream_t sb = ok2 ? s2 : (cudaStream_t)0;

    if (ok2) {
        cudaEventRecord(evFork, 0);
        cudaStreamWaitEvent(s2, evFork, 0);
    }

    // CSR chain (side stream)
    zero_deg_kernel<<<(NN + 255) / 256, 256, 0, sb>>>();
    histo_kernel<<<(EE + 255) / 256, 256, 0, sb>>>(dst);
    scan_all_kernel<<<1, 1024, 0, sb>>>();
    scatter_kernel<<<(EE + 255) / 256, 256, 0, sb>>>(src, dst);

    // GEMM chain (main stream)
    wprep_kernel<<<(IN_F * HC + 255) / 256, 256>>>(W);
    gemm_feat_tc_kernel<<<(NN + 127) / 128, 256>>>(x, attn_l, attn_r);

    if (ok2) {
        cudaEventRecord(evJoin, s2);
        cudaStreamWaitEvent(0, evJoin, 0);
    }

    aggregate_fused_kernel<<<(NN * 32 + 255) / 256, 256>>>(bias, out);
}

// round 12
// speedup vs baseline: 1.4179x; 1.4179x over previous
#include <cstdint>
#include <cuda_runtime.h>
#include <cuda_fp16.h>
#include <cuda_bf16.h>

#define NN 100000
#define EE 1600000
#define IN_F 256
#define HH 4
#define CC 32
#define HC 128           // HH*CC
#define NB 98            // ceil(NN/1024) scan blocks
#define AST 40           // smem stride in half (80B rows: conflict-free ldmatrix)

// ---------------- device scratch (no allocations allowed) ----------------
__device__ __half g_feat_h[NN * HC];  // projected features [N, H*C] (fp16)
__device__ float g_el[NN * HH];       // left attention logits  [N,H]
__device__ float g_er[NN * HH];       // right attention logits [N,H]
__device__ int   g_deg[NN];           // in-degree histogram
__device__ int   g_rowoff[NN + 1];    // CSR row offsets (by dst)
__device__ int   g_cursor[NN];        // scatter cursors
__device__ int   g_blocksums[128];    // scan partials
__device__ int   g_srcsorted[EE];     // src node id per edge, grouped by dst
__device__ __half g_Wt[HC * IN_F];    // W^T fp16: [n=128][k=256]

// ---------------- kernel 0: W -> W^T fp16 ----------------
__global__ void wprep_kernel(const float* __restrict__ W) {
    int i = blockIdx.x * blockDim.x + threadIdx.x;  // over 256*128
    if (i >= IN_F * HC) return;
    int k = i >> 7, n = i & 127;
    g_Wt[n * IN_F + k] = __float2half_rn(W[i]);
}

// ---------------- kernel 1: feat = x @ W via fp16 tensor cores ----------
// Block: 128x128 out tile, 256 thr = 8 warps as 4(m) x 2(n); warp tile 32x64.
// Fused epilogue computes el/er per (row, head) via quad-shfl reduction.
__global__ __launch_bounds__(256) void gemm_feat_tc_kernel(
    const float* __restrict__ x,
    const float* __restrict__ attn_l, const float* __restrict__ attn_r)
{
    __shared__ __half As[128][AST];
    __shared__ __half Bs[128][AST];

    int tid = threadIdx.x, lane = tid & 31, wid = tid >> 5;
    int warp_m = wid >> 1;          // 0..3
    int warp_n = wid & 1;           // 0..1
    int row0 = blockIdx.x * 128;

    float acc[2][8][4];
#pragma unroll
    for (int im = 0; im < 2; im++)
#pragma unroll
        for (int jn = 0; jn < 8; jn++)
#pragma unroll
            for (int r = 0; r < 4; r++) acc[im][jn][r] = 0.f;

    for (int k0 = 0; k0 < IN_F; k0 += 32) {
        // x tile: 128 rows x 32 k, fp32 -> fp16
#pragma unroll
        for (int l = 0; l < 4; l++) {
            int idx = tid + l * 256;            // 0..1023 float4 slots
            int r = idx >> 3, c4 = (idx & 7) << 2;
            int row = row0 + r;
            float4 v = make_float4(0.f, 0.f, 0.f, 0.f);
            if (row < NN)
                v = *reinterpret_cast<const float4*>(&x[(size_t)row * IN_F + k0 + c4]);
            *reinterpret_cast<__half2*>(&As[r][c4])     = __floats2half2_rn(v.x, v.y);
            *reinterpret_cast<__half2*>(&As[r][c4 + 2]) = __floats2half2_rn(v.z, v.w);
        }
        // W tile: [128 n][32 k] fp16, preconverted
        {
#pragma unroll
            for (int l = 0; l < 2; l++) {
                int s = tid + l * 256;
                int n = s >> 2, k8 = (s & 3) << 3;
                *reinterpret_cast<uint4*>(&Bs[n][k8]) =
                    *reinterpret_cast<const uint4*>(&g_Wt[n * IN_F + k0 + k8]);
            }
        }
        __syncthreads();

#pragma unroll
        for (int kk = 0; kk < 32; kk += 16) {
            uint32_t af[2][4];
#pragma unroll
            for (int im = 0; im < 2; im++) {
                uint32_t adr = (uint32_t)__cvta_generic_to_shared(
                    &As[warp_m * 32 + im * 16 + (lane & 15)][kk + ((lane >> 4) << 3)]);
                asm volatile("ldmatrix.sync.aligned.m8n8.x4.shared.b16 {%0,%1,%2,%3}, [%4];"
                             : "=r"(af[im][0]), "=r"(af[im][1]), "=r"(af[im][2]), "=r"(af[im][3])
                             : "r"(adr));
            }
#pragma unroll
            for (int jn = 0; jn < 8; jn++) {
                int nb = warp_n * 64 + jn * 8;
                uint32_t bf[2];
                uint32_t adr_b = (uint32_t)__cvta_generic_to_shared(
                    &Bs[nb + (lane & 7)][kk + (((lane >> 3) & 1) << 3)]);
                asm volatile("ldmatrix.sync.aligned.m8n8.x2.shared.b16 {%0,%1}, [%2];"
                             : "=r"(bf[0]), "=r"(bf[1]) : "r"(adr_b));
#pragma unroll
                for (int im = 0; im < 2; im++) {
                    float* c = acc[im][jn];
                    asm volatile(
                        "mma.sync.aligned.m16n8k16.row.col.f32.f16.f16.f32 "
                        "{%0,%1,%2,%3}, {%4,%5,%6,%7}, {%8,%9}, {%0,%1,%2,%3};"
                        : "+f"(c[0]), "+f"(c[1]), "+f"(c[2]), "+f"(c[3])
                        : "r"(af[im][0]), "r"(af[im][1]), "r"(af[im][2]), "r"(af[im][3]),
                          "r"(bf[0]), "r"(bf[1]));
                }
            }
        }
        __syncthreads();
    }

    // ---- epilogue: store feat (fp16), compute el/er per (row, head) ----
    int quad = lane >> 2, tc = lane & 3;
    float pel[2][2][2], per[2][2][2];   // [im][rowhalf][headhalf]
#pragma unroll
    for (int im = 0; im < 2; im++)
#pragma unroll
        for (int rh = 0; rh < 2; rh++)
#pragma unroll
            for (int hh = 0; hh < 2; hh++) { pel[im][rh][hh] = 0.f; per[im][rh][hh] = 0.f; }

#pragma unroll
    for (int im = 0; im < 2; im++) {
        int rowA = row0 + warp_m * 32 + im * 16 + quad;
#pragma unroll
        for (int jn = 0; jn < 8; jn++) {
            int col = warp_n * 64 + jn * 8 + tc * 2;
            int hh = jn >> 2;
            float* c = acc[im][jn];
            float a0 = attn_l[col], a1 = attn_l[col + 1];
            float b0 = attn_r[col], b1 = attn_r[col + 1];
            pel[im][0][hh] += c[0] * a0 + c[1] * a1;
            per[im][0][hh] += c[0] * b0 + c[1] * b1;
            pel[im][1][hh] += c[2] * a0 + c[3] * a1;
            per[im][1][hh] += c[2] * b0 + c[3] * b1;
            if (rowA < NN)
                *reinterpret_cast<__half2*>(&g_feat_h[(size_t)rowA * HC + col]) =
                    __floats2half2_rn(c[0], c[1]);
            if (rowA + 8 < NN)
                *reinterpret_cast<__half2*>(&g_feat_h[(size_t)(rowA + 8) * HC + col]) =
                    __floats2half2_rn(c[2], c[3]);
        }
    }
#pragma unroll
    for (int im = 0; im < 2; im++)
#pragma unroll
        for (int rh = 0; rh < 2; rh++)
#pragma unroll
            for (int hh = 0; hh < 2; hh++) {
                float e = pel[im][rh][hh], r = per[im][rh][hh];
                e += __shfl_xor_sync(0xffffffffu, e, 1);
                e += __shfl_xor_sync(0xffffffffu, e, 2);
                r += __shfl_xor_sync(0xffffffffu, r, 1);
                r += __shfl_xor_sync(0xffffffffu, r, 2);
                if (tc == 0) {
                    int row = row0 + warp_m * 32 + im * 16 + quad + rh * 8;
                    int head = warp_n * 2 + hh;
                    if (row < NN) {
                        g_el[row * HH + head] = e;
                        g_er[row * HH + head] = r;
                    }
                }
            }
}

// ---------------- CSR build ----------------
__global__ void zero_deg_kernel() {
    int i = blockIdx.x * blockDim.x + threadIdx.x;
    if (i < NN) g_deg[i] = 0;
}

__global__ void histo_kernel(const int* __restrict__ dst) {
    int e = blockIdx.x * blockDim.x + threadIdx.x;
    if (e < EE) atomicAdd(&g_deg[dst[e]], 1);
}

__global__ __launch_bounds__(1024) void scan1_kernel() {
    __shared__ int sh[1024];
    int i = blockIdx.x * 1024 + threadIdx.x;
    int v = (i < NN) ? g_deg[i] : 0;
    sh[threadIdx.x] = v;
    __syncthreads();
#pragma unroll
    for (int off = 1; off < 1024; off <<= 1) {
        int t = (threadIdx.x >= off) ? sh[threadIdx.x - off] : 0;
        __syncthreads();
        sh[threadIdx.x] += t;
        __syncthreads();
    }
    if (i < NN) g_rowoff[i] = sh[threadIdx.x] - v;        // exclusive
    if (threadIdx.x == 1023) g_blocksums[blockIdx.x] = sh[1023];
}

__global__ void scan2_kernel() {
    __shared__ int sh[128];
    int v = (threadIdx.x < NB) ? g_blocksums[threadIdx.x] : 0;
    sh[threadIdx.x] = v;
    __syncthreads();
#pragma unroll
    for (int off = 1; off < 128; off <<= 1) {
        int t = (threadIdx.x >= off) ? sh[threadIdx.x - off] : 0;
        __syncthreads();
        sh[threadIdx.x] += t;
        __syncthreads();
    }
    if (threadIdx.x < NB) g_blocksums[threadIdx.x] = sh[threadIdx.x] - v;  // exclusive
}

__global__ __launch_bounds__(1024) void scan3_kernel() {
    int i = blockIdx.x * 1024 + threadIdx.x;
    if (i < NN) {
        int v = g_rowoff[i] + g_blocksums[blockIdx.x];
        g_rowoff[i] = v;
        g_cursor[i] = v;
    }
    if (i == 0) g_rowoff[NN] = EE;
}

__global__ void scatter_kernel(const int* __restrict__ src,
                               const int* __restrict__ dst) {
    int e = blockIdx.x * blockDim.x + threadIdx.x;
    if (e >= EE) return;
    int pos = atomicAdd(&g_cursor[dst[e]], 1);
    g_srcsorted[pos] = src[e];
}

// ------- fused single-pass softmax-aggregate + head-mean + relu -------
__global__ __launch_bounds__(256) void aggregate_fused_kernel(
    const float* __restrict__ bias, float* __restrict__ out)
{
    __shared__ float sh_ex[8][32][4];   // [warp][edge-in-chunk][head]
    int wslot = threadIdx.x >> 5;
    int warp = (blockIdx.x * blockDim.x + threadIdx.x) >> 5;
    int lane = threadIdx.x & 31;
    if (warp >= NN) return;
    int n = warp;
    int head = lane >> 3;

    int start = g_rowoff[n];
    int end   = g_rowoff[n + 1];

    float4 er4 = *reinterpret_cast<const float4*>(&g_er[n * HH]);

    float4 den = make_float4(0.f, 0.f, 0.f, 0.f);
    float4 acc = make_float4(0.f, 0.f, 0.f, 0.f);
    const uint2* feat2 = reinterpret_cast<const uint2*>(g_feat_h);

    for (int j0 = start; j0 < end; j0 += 32) {
        int jj = j0 + lane;
        int sj = 0;
        float4 ex4 = make_float4(0.f, 0.f, 0.f, 0.f);
        if (jj < end) {
            sj = g_srcsorted[jj];
            float4 el4 = *reinterpret_cast<const float4*>(&g_el[sj * HH]);
            float v0 = el4.x + er4.x, v1 = el4.y + er4.y;
            float v2 = el4.z + er4.z, v3 = el4.w + er4.w;
            v0 = v0 > 0.f ? v0 : 0.2f * v0;
            v1 = v1 > 0.f ? v1 : 0.2f * v1;
            v2 = v2 > 0.f ? v2 : 0.2f * v2;
            v3 = v3 > 0.f ? v3 : 0.2f * v3;
            ex4 = make_float4(__expf(v0), __expf(v1), __expf(v2), __expf(v3));
            den.x += ex4.x; den.y += ex4.y; den.z += ex4.z; den.w += ex4.w;
        }
        *reinterpret_cast<float4*>(&sh_ex[wslot][lane][0]) = ex4;
        __syncwarp();
        int m = end - j0; if (m > 32) m = 32;
        for (int t = 0; t < m; t++) {
            int s = __shfl_sync(0xffffffffu, sj, t);
            float num = sh_ex[wslot][t][head];          // broadcast LDS
            uint2 u = feat2[(size_t)s * 32 + lane];     // 8B fp16 gather
            float2 f01 = __half22float2(*reinterpret_cast<__half2*>(&u.x));
            float2 f23 = __half22float2(*reinterpret_cast<__half2*>(&u.y));
            acc.x += num * f01.x; acc.y += num * f01.y;
            acc.z += num * f23.x; acc.w += num * f23.y;
        }
        __syncwarp();
    }

#pragma unroll
    for (int off = 16; off > 0; off >>= 1) {
        den.x += __shfl_xor_sync(0xffffffffu, den.x, off);
        den.y += __shfl_xor_sync(0xffffffffu, den.y, off);
        den.z += __shfl_xor_sync(0xffffffffu, den.z, off);
        den.w += __shfl_xor_sync(0xffffffffu, den.w, off);
    }
    float dmine = (head == 0) ? den.x : (head == 1) ? den.y
                 : (head == 2) ? den.z : den.w;
    float rinv = (dmine > 0.f) ? __fdividef(1.f, dmine) : 0.f;
    acc.x *= rinv; acc.y *= rinv; acc.z *= rinv; acc.w *= rinv;

#pragma unroll
    for (int off = 8; off <= 16; off <<= 1) {
        acc.x += __shfl_xor_sync(0xffffffffu, acc.x, off);
        acc.y += __shfl_xor_sync(0xffffffffu, acc.y, off);
        acc.z += __shfl_xor_sync(0xffffffffu, acc.z, off);
        acc.w += __shfl_xor_sync(0xffffffffu, acc.w, off);
    }
    if (lane < 8) {
        float bs[4] = {0.f, 0.f, 0.f, 0.f};
#pragma unroll
        for (int h = 0; h < HH; h++) {
#pragma unroll
            for (int k = 0; k < 4; k++) bs[k] += bias[h * CC + lane * 4 + k];
        }
        float4 o;
        o.x = fmaxf(0.25f * (acc.x + bs[0]), 0.f);
        o.y = fmaxf(0.25f * (acc.y + bs[1]), 0.f);
        o.z = fmaxf(0.25f * (acc.z + bs[2]), 0.f);
        o.w = fmaxf(0.25f * (acc.w + bs[3]), 0.f);
        reinterpret_cast<float4*>(out)[n * 8 + lane] = o;
    }
}

// ---------------- launch: single stream, serial chain ----------------
extern "C" void kernel_launch(void* const* d_in, const int* in_sizes, int n_in,
                              void* d_out, int out_size)
{
    const float* x      = (const float*)d_in[0];
    const int*   src    = (const int*)d_in[1];
    const int*   dst    = (const int*)d_in[2];
    const float* W      = (const float*)d_in[3];
    const float* attn_l = (const float*)d_in[4];
    const float* attn_r = (const float*)d_in[5];
    const float* bias   = (const float*)d_in[6];
    float* out = (float*)d_out;

    wprep_kernel<<<(IN_F * HC + 255) / 256, 256>>>(W);
    gemm_feat_tc_kernel<<<(NN + 127) / 128, 256>>>(x, attn_l, attn_r);

    zero_deg_kernel<<<(NN + 255) / 256, 256>>>();
    histo_kernel<<<(EE + 255) / 256, 256>>>(dst);
    scan1_kernel<<<NB, 1024>>>();
    scan2_kernel<<<1, 128>>>();
    scan3_kernel<<<NB, 1024>>>();
    scatter_kernel<<<(EE + 255) / 256, 256>>>(src, dst);

    aggregate_fused_kernel<<<(NN * 32 + 255) / 256, 256>>>(bias, out);
}

// round 14
// speedup vs baseline: 1.4863x; 1.0482x over previous
#include <cstdint>
#include <cuda_runtime.h>
#include <cuda_fp16.h>
#include <cuda_bf16.h>

#define NN 100000
#define EE 1600000
#define IN_F 256
#define HH 4
#define CC 32
#define HC 128           // HH*CC
#define NB 98            // ceil(NN/1024) scan blocks
#define AST 40           // smem stride in half (80B rows: conflict-free ldmatrix)

// ---------------- device scratch (no allocations allowed) ----------------
__device__ __half g_feat_h[NN * HC];  // projected features [N, H*C] (fp16)
__device__ float g_el[NN * HH];       // left attention logits  [N,H]
__device__ float g_er[NN * HH];       // right attention logits [N,H]
__device__ int   g_deg[NN];           // in-degree histogram
__device__ int   g_rowoff[NN + 1];    // CSR row offsets (by dst)
__device__ int   g_cursor[NN];        // scatter cursors
__device__ int   g_blocksums[128];    // scan partials
__device__ int   g_srcsorted[EE];     // src node id per edge, grouped by dst
__device__ __half g_Wt[HC * IN_F];    // W^T fp16: [n=128][k=256]

// ------- kernel 0: W -> W^T fp16 AND zero the degree histogram -------
__global__ void prep_kernel(const float* __restrict__ W) {
    int i = blockIdx.x * blockDim.x + threadIdx.x;
    if (i < IN_F * HC) {
        int k = i >> 7, n = i & 127;
        g_Wt[n * IN_F + k] = __float2half_rn(W[i]);
    }
    if (i < NN) g_deg[i] = 0;
}

// ---------------- kernel 1: feat = x @ W via fp16 tensor cores ----------
// 128x128 out tile, 8 warps (4m x 2n), warp tile 32x64.
// 2-stage smem double buffer: LDG(i+1) -> regs overlaps compute(i); one sync/iter.
// Fused epilogue computes el/er per (row, head) via quad-shfl reduction.
__global__ __launch_bounds__(256) void gemm_feat_tc_kernel(
    const float* __restrict__ x,
    const float* __restrict__ attn_l, const float* __restrict__ attn_r)
{
    __shared__ __half As[2][128][AST];
    __shared__ __half Bs[2][128][AST];

    int tid = threadIdx.x, lane = tid & 31, wid = tid >> 5;
    int warp_m = wid >> 1;          // 0..3
    int warp_n = wid & 1;           // 0..1
    int row0 = blockIdx.x * 128;

    float acc[2][8][4];
#pragma unroll
    for (int im = 0; im < 2; im++)
#pragma unroll
        for (int jn = 0; jn < 8; jn++)
#pragma unroll
            for (int r = 0; r < 4; r++) acc[im][jn][r] = 0.f;

    float4 av[4];     // staged x tile (fp32, converted at STS)
    uint4  bv[2];     // staged W tile (fp16 packed)

    auto ldg_tiles = [&](int k0) {
#pragma unroll
        for (int l = 0; l < 4; l++) {
            int idx = tid + l * 256;            // 0..1023 float4 slots
            int r = idx >> 3, c4 = (idx & 7) << 2;
            int row = row0 + r;
            av[l] = make_float4(0.f, 0.f, 0.f, 0.f);
            if (row < NN)
                av[l] = *reinterpret_cast<const float4*>(&x[(size_t)row * IN_F + k0 + c4]);
        }
#pragma unroll
        for (int l = 0; l < 2; l++) {
            int s = tid + l * 256;              // 0..511 uint4 slots
            int n = s >> 2, k8 = (s & 3) << 3;
            bv[l] = *reinterpret_cast<const uint4*>(&g_Wt[n * IN_F + k0 + k8]);
        }
    };
    auto sts_tiles = [&](int st) {
#pragma unroll
        for (int l = 0; l < 4; l++) {
            int idx = tid + l * 256;
            int r = idx >> 3, c4 = (idx & 7) << 2;
            *reinterpret_cast<__half2*>(&As[st][r][c4])     = __floats2half2_rn(av[l].x, av[l].y);
            *reinterpret_cast<__half2*>(&As[st][r][c4 + 2]) = __floats2half2_rn(av[l].z, av[l].w);
        }
#pragma unroll
        for (int l = 0; l < 2; l++) {
            int s = tid + l * 256;
            int n = s >> 2, k8 = (s & 3) << 3;
            *reinterpret_cast<uint4*>(&Bs[st][n][k8]) = bv[l];
        }
    };

    const int NK = IN_F / 32;   // 8
    ldg_tiles(0);
    sts_tiles(0);
    __syncthreads();

    for (int i = 0; i < NK; i++) {
        if (i + 1 < NK) ldg_tiles((i + 1) * 32);
        int st = i & 1;

#pragma unroll
        for (int kk = 0; kk < 32; kk += 16) {
            uint32_t af[2][4];
#pragma unroll
            for (int im = 0; im < 2; im++) {
                uint32_t adr = (uint32_t)__cvta_generic_to_shared(
                    &As[st][warp_m * 32 + im * 16 + (lane & 15)][kk + ((lane >> 4) << 3)]);
                asm volatile("ldmatrix.sync.aligned.m8n8.x4.shared.b16 {%0,%1,%2,%3}, [%4];"
                             : "=r"(af[im][0]), "=r"(af[im][1]), "=r"(af[im][2]), "=r"(af[im][3])
                             : "r"(adr));
            }
#pragma unroll
            for (int jn = 0; jn < 8; jn++) {
                int nb = warp_n * 64 + jn * 8;
                uint32_t bf[2];
                uint32_t adr_b = (uint32_t)__cvta_generic_to_shared(
                    &Bs[st][nb + (lane & 7)][kk + (((lane >> 3) & 1) << 3)]);
                asm volatile("ldmatrix.sync.aligned.m8n8.x2.shared.b16 {%0,%1}, [%2];"
                             : "=r"(bf[0]), "=r"(bf[1]) : "r"(adr_b));
#pragma unroll
                for (int im = 0; im < 2; im++) {
                    float* c = acc[im][jn];
                    asm volatile(
                        "mma.sync.aligned.m16n8k16.row.col.f32.f16.f16.f32 "
                        "{%0,%1,%2,%3}, {%4,%5,%6,%7}, {%8,%9}, {%0,%1,%2,%3};"
                        : "+f"(c[0]), "+f"(c[1]), "+f"(c[2]), "+f"(c[3])
                        : "r"(af[im][0]), "r"(af[im][1]), "r"(af[im][2]), "r"(af[im][3]),
                          "r"(bf[0]), "r"(bf[1]));
                }
            }
        }

        if (i + 1 < NK) sts_tiles((i + 1) & 1);  // writes other buffer; its readers
                                                 // finished before last iter's sync
        __syncthreads();
    }

    // ---- epilogue: store feat (fp16), compute el/er per (row, head) ----
    int quad = lane >> 2, tc = lane & 3;
    float pel[2][2][2], per[2][2][2];   // [im][rowhalf][headhalf]
#pragma unroll
    for (int im = 0; im < 2; im++)
#pragma unroll
        for (int rh = 0; rh < 2; rh++)
#pragma unroll
            for (int hh = 0; hh < 2; hh++) { pel[im][rh][hh] = 0.f; per[im][rh][hh] = 0.f; }

#pragma unroll
    for (int im = 0; im < 2; im++) {
        int rowA = row0 + warp_m * 32 + im * 16 + quad;
#pragma unroll
        for (int jn = 0; jn < 8; jn++) {
            int col = warp_n * 64 + jn * 8 + tc * 2;
            int hh = jn >> 2;
            float* c = acc[im][jn];
            float a0 = attn_l[col], a1 = attn_l[col + 1];
            float b0 = attn_r[col], b1 = attn_r[col + 1];
            pel[im][0][hh] += c[0] * a0 + c[1] * a1;
            per[im][0][hh] += c[0] * b0 + c[1] * b1;
            pel[im][1][hh] += c[2] * a0 + c[3] * a1;
            per[im][1][hh] += c[2] * b0 + c[3] * b1;
            if (rowA < NN)
                *reinterpret_cast<__half2*>(&g_feat_h[(size_t)rowA * HC + col]) =
                    __floats2half2_rn(c[0], c[1]);
            if (rowA + 8 < NN)
                *reinterpret_cast<__half2*>(&g_feat_h[(size_t)(rowA + 8) * HC + col]) =
                    __floats2half2_rn(c[2], c[3]);
        }
    }
#pragma unroll
    for (int im = 0; im < 2; im++)
#pragma unroll
        for (int rh = 0; rh < 2; rh++)
#pragma unroll
            for (int hh = 0; hh < 2; hh++) {
                float e = pel[im][rh][hh], r = per[im][rh][hh];
                e += __shfl_xor_sync(0xffffffffu, e, 1);
                e += __shfl_xor_sync(0xffffffffu, e, 2);
                r += __shfl_xor_sync(0xffffffffu, r, 1);
                r += __shfl_xor_sync(0xffffffffu, r, 2);
                if (tc == 0) {
                    int row = row0 + warp_m * 32 + im * 16 + quad + rh * 8;
                    int head = warp_n * 2 + hh;
                    if (row < NN) {
                        g_el[row * HH + head] = e;
                        g_er[row * HH + head] = r;
                    }
                }
            }
}

// ---------------- CSR build (4 edges per thread) ----------------
__global__ void histo_kernel(const int* __restrict__ dst) {
    int i = blockIdx.x * blockDim.x + threadIdx.x;
    if (i >= EE / 4) return;
    int4 d = reinterpret_cast<const int4*>(dst)[i];
    atomicAdd(&g_deg[d.x], 1);
    atomicAdd(&g_deg[d.y], 1);
    atomicAdd(&g_deg[d.z], 1);
    atomicAdd(&g_deg[d.w], 1);
}

__global__ __launch_bounds__(1024) void scan1_kernel() {
    __shared__ int sh[1024];
    int i = blockIdx.x * 1024 + threadIdx.x;
    int v = (i < NN) ? g_deg[i] : 0;
    sh[threadIdx.x] = v;
    __syncthreads();
#pragma unroll
    for (int off = 1; off < 1024; off <<= 1) {
        int t = (threadIdx.x >= off) ? sh[threadIdx.x - off] : 0;
        __syncthreads();
        sh[threadIdx.x] += t;
        __syncthreads();
    }
    if (i < NN) g_rowoff[i] = sh[threadIdx.x] - v;        // exclusive
    if (threadIdx.x == 1023) g_blocksums[blockIdx.x] = sh[1023];
}

__global__ void scan2_kernel() {
    __shared__ int sh[128];
    int v = (threadIdx.x < NB) ? g_blocksums[threadIdx.x] : 0;
    sh[threadIdx.x] = v;
    __syncthreads();
#pragma unroll
    for (int off = 1; off < 128; off <<= 1) {
        int t = (threadIdx.x >= off) ? sh[threadIdx.x - off] : 0;
        __syncthreads();
        sh[threadIdx.x] += t;
        __syncthreads();
    }
    if (threadIdx.x < NB) g_blocksums[threadIdx.x] = sh[threadIdx.x] - v;  // exclusive
}

__global__ __launch_bounds__(1024) void scan3_kernel() {
    int i = blockIdx.x * 1024 + threadIdx.x;
    if (i < NN) {
        int v = g_rowoff[i] + g_blocksums[blockIdx.x];
        g_rowoff[i] = v;
        g_cursor[i] = v;
    }
    if (i == 0) g_rowoff[NN] = EE;
}

__global__ void scatter_kernel(const int* __restrict__ src,
                               const int* __restrict__ dst) {
    int i = blockIdx.x * blockDim.x + threadIdx.x;
    if (i >= EE / 4) return;
    int4 s4 = reinterpret_cast<const int4*>(src)[i];
    int4 d4 = reinterpret_cast<const int4*>(dst)[i];
    int p;
    p = atomicAdd(&g_cursor[d4.x], 1); g_srcsorted[p] = s4.x;
    p = atomicAdd(&g_cursor[d4.y], 1); g_srcsorted[p] = s4.y;
    p = atomicAdd(&g_cursor[d4.z], 1); g_srcsorted[p] = s4.z;
    p = atomicAdd(&g_cursor[d4.w], 1); g_srcsorted[p] = s4.w;
}

// ------- fused single-pass softmax-aggregate + head-mean + relu -------
__global__ __launch_bounds__(256) void aggregate_fused_kernel(
    const float* __restrict__ bias, float* __restrict__ out)
{
    __shared__ float sh_ex[8][32][4];   // [warp][edge-in-chunk][head]
    int wslot = threadIdx.x >> 5;
    int warp = (blockIdx.x * blockDim.x + threadIdx.x) >> 5;
    int lane = threadIdx.x & 31;
    if (warp >= NN) return;
    int n = warp;
    int head = lane >> 3;

    int start = g_rowoff[n];
    int end   = g_rowoff[n + 1];

    float4 er4 = *reinterpret_cast<const float4*>(&g_er[n * HH]);

    float4 den = make_float4(0.f, 0.f, 0.f, 0.f);
    float4 acc = make_float4(0.f, 0.f, 0.f, 0.f);
    const uint2* feat2 = reinterpret_cast<const uint2*>(g_feat_h);

    for (int j0 = start; j0 < end; j0 += 32) {
        int jj = j0 + lane;
        int sj = 0;
        float4 ex4 = make_float4(0.f, 0.f, 0.f, 0.f);
        if (jj < end) {
            sj = g_srcsorted[jj];
            float4 el4 = *reinterpret_cast<const float4*>(&g_el[sj * HH]);
            float v0 = el4.x + er4.x, v1 = el4.y + er4.y;
            float v2 = el4.z + er4.z, v3 = el4.w + er4.w;
            v0 = v0 > 0.f ? v0 : 0.2f * v0;
            v1 = v1 > 0.f ? v1 : 0.2f * v1;
            v2 = v2 > 0.f ? v2 : 0.2f * v2;
            v3 = v3 > 0.f ? v3 : 0.2f * v3;
            ex4 = make_float4(__expf(v0), __expf(v1), __expf(v2), __expf(v3));
            den.x += ex4.x; den.y += ex4.y; den.z += ex4.z; den.w += ex4.w;
        }
        *reinterpret_cast<float4*>(&sh_ex[wslot][lane][0]) = ex4;
        __syncwarp();
        int m = end - j0; if (m > 32) m = 32;
        for (int t = 0; t < m; t++) {
            int s = __shfl_sync(0xffffffffu, sj, t);
            float num = sh_ex[wslot][t][head];          // broadcast LDS
            uint2 u = feat2[(size_t)s * 32 + lane];     // 8B fp16 gather
            float2 f01 = __half22float2(*reinterpret_cast<__half2*>(&u.x));
            float2 f23 = __half22float2(*reinterpret_cast<__half2*>(&u.y));
            acc.x += num * f01.x; acc.y += num * f01.y;
            acc.z += num * f23.x; acc.w += num * f23.y;
        }
        __syncwarp();
    }

#pragma unroll
    for (int off = 16; off > 0; off >>= 1) {
        den.x += __shfl_xor_sync(0xffffffffu, den.x, off);
        den.y += __shfl_xor_sync(0xffffffffu, den.y, off);
        den.z += __shfl_xor_sync(0xffffffffu, den.z, off);
        den.w += __shfl_xor_sync(0xffffffffu, den.w, off);
    }
    float dmine = (head == 0) ? den.x : (head == 1) ? den.y
                 : (head == 2) ? den.z : den.w;
    float rinv = (dmine > 0.f) ? __fdividef(1.f, dmine) : 0.f;
    acc.x *= rinv; acc.y *= rinv; acc.z *= rinv; acc.w *= rinv;

#pragma unroll
    for (int off = 8; off <= 16; off <<= 1) {
        acc.x += __shfl_xor_sync(0xffffffffu, acc.x, off);
        acc.y += __shfl_xor_sync(0xffffffffu, acc.y, off);
        acc.z += __shfl_xor_sync(0xffffffffu, acc.z, off);
        acc.w += __shfl_xor_sync(0xffffffffu, acc.w, off);
    }
    if (lane < 8) {
        float bs[4] = {0.f, 0.f, 0.f, 0.f};
#pragma unroll
        for (int h = 0; h < HH; h++) {
#pragma unroll
            for (int k = 0; k < 4; k++) bs[k] += bias[h * CC + lane * 4 + k];
        }
        float4 o;
        o.x = fmaxf(0.25f * (acc.x + bs[0]), 0.f);
        o.y = fmaxf(0.25f * (acc.y + bs[1]), 0.f);
        o.z = fmaxf(0.25f * (acc.z + bs[2]), 0.f);
        o.w = fmaxf(0.25f * (acc.w + bs[3]), 0.f);
        reinterpret_cast<float4*>(out)[n * 8 + lane] = o;
    }
}

// ---------------- launch: single stream, serial chain ----------------
extern "C" void kernel_launch(void* const* d_in, const int* in_sizes, int n_in,
                              void* d_out, int out_size)
{
    const float* x      = (const float*)d_in[0];
    const int*   src    = (const int*)d_in[1];
    const int*   dst    = (const int*)d_in[2];
    const float* W      = (const float*)d_in[3];
    const float* attn_l = (const float*)d_in[4];
    const float* attn_r = (const float*)d_in[5];
    const float* bias   = (const float*)d_in[6];
    float* out = (float*)d_out;

    prep_kernel<<<(NN + 255) / 256, 256>>>(W);
    gemm_feat_tc_kernel<<<(NN + 127) / 128, 256>>>(x, attn_l, attn_r);

    histo_kernel<<<(EE / 4 + 255) / 256, 256>>>(dst);
    scan1_kernel<<<NB, 1024>>>();
    scan2_kernel<<<1, 128>>>();
    scan3_kernel<<<NB, 1024>>>();
    scatter_kernel<<<(EE / 4 + 255) / 256, 256>>>(src, dst);

    aggregate_fused_kernel<<<(NN * 32 + 255) / 256, 256>>>(bias, out);
}

// round 15
// speedup vs baseline: 1.5038x; 1.0118x over previous
#include <cstdint>
#include <cuda_runtime.h>
#include <cuda_fp16.h>
#include <cuda_bf16.h>

#define NN 100000
#define EE 1600000
#define IN_F 256
#define HH 4
#define CC 32
#define HC 128           // HH*CC
#define NB 98            // ceil(NN/1024) scan blocks
#define AST 40           // smem stride in half (80B rows: conflict-free ldmatrix)

// ---------------- device scratch (no allocations allowed) ----------------
__device__ __half g_feat_h[NN * HC];  // projected features [N, H*C] (fp16)
__device__ float g_el[NN * HH];       // left attention logits  [N,H]
__device__ float g_er[NN * HH];       // right attention logits [N,H]
__device__ int   g_deg[NN];           // in-degree histogram
__device__ int   g_rowoff[NN + 1];    // CSR row offsets (by dst)
__device__ int   g_cursor[NN];        // scatter cursors
__device__ int   g_blocksums[128];    // per-block totals from scan1 (raw)
__device__ int   g_srcsorted[EE];     // src node id per edge, grouped by dst
__device__ __half g_Wt[HC * IN_F];    // W^T fp16: [n=128][k=256]

// ------- kernel 0: W -> W^T fp16 AND zero the degree histogram -------
__global__ void prep_kernel(const float* __restrict__ W) {
    int i = blockIdx.x * blockDim.x + threadIdx.x;
    if (i < IN_F * HC) {
        int k = i >> 7, n = i & 127;
        g_Wt[n * IN_F + k] = __float2half_rn(W[i]);
    }
    if (i < NN) g_deg[i] = 0;
}

// ---------------- kernel 1: feat = x @ W via fp16 tensor cores ----------
// 128x128 out tile, 8 warps (4m x 2n), warp tile 32x64.
// 2-stage smem double buffer: LDG(i+1) -> regs overlaps compute(i); one sync/iter.
// Fused epilogue computes el/er per (row, head) via quad-shfl reduction.
__global__ __launch_bounds__(256) void gemm_feat_tc_kernel(
    const float* __restrict__ x,
    const float* __restrict__ attn_l, const float* __restrict__ attn_r)
{
    __shared__ __half As[2][128][AST];
    __shared__ __half Bs[2][128][AST];

    int tid = threadIdx.x, lane = tid & 31, wid = tid >> 5;
    int warp_m = wid >> 1;          // 0..3
    int warp_n = wid & 1;           // 0..1
    int row0 = blockIdx.x * 128;

    float acc[2][8][4];
#pragma unroll
    for (int im = 0; im < 2; im++)
#pragma unroll
        for (int jn = 0; jn < 8; jn++)
#pragma unroll
            for (int r = 0; r < 4; r++) acc[im][jn][r] = 0.f;

    float4 av[4];     // staged x tile (fp32, converted at STS)
    uint4  bv[2];     // staged W tile (fp16 packed)

    auto ldg_tiles = [&](int k0) {
#pragma unroll
        for (int l = 0; l < 4; l++) {
            int idx = tid + l * 256;            // 0..1023 float4 slots
            int r = idx >> 3, c4 = (idx & 7) << 2;
            int row = row0 + r;
            av[l] = make_float4(0.f, 0.f, 0.f, 0.f);
            if (row < NN)
                av[l] = *reinterpret_cast<const float4*>(&x[(size_t)row * IN_F + k0 + c4]);
        }
#pragma unroll
        for (int l = 0; l < 2; l++) {
            int s = tid + l * 256;              // 0..511 uint4 slots
            int n = s >> 2, k8 = (s & 3) << 3;
            bv[l] = *reinterpret_cast<const uint4*>(&g_Wt[n * IN_F + k0 + k8]);
        }
    };
    auto sts_tiles = [&](int st) {
#pragma unroll
        for (int l = 0; l < 4; l++) {
            int idx = tid + l * 256;
            int r = idx >> 3, c4 = (idx & 7) << 2;
            *reinterpret_cast<__half2*>(&As[st][r][c4])     = __floats2half2_rn(av[l].x, av[l].y);
            *reinterpret_cast<__half2*>(&As[st][r][c4 + 2]) = __floats2half2_rn(av[l].z, av[l].w);
        }
#pragma unroll
        for (int l = 0; l < 2; l++) {
            int s = tid + l * 256;
            int n = s >> 2, k8 = (s & 3) << 3;
            *reinterpret_cast<uint4*>(&Bs[st][n][k8]) = bv[l];
        }
    };

    const int NK = IN_F / 32;   // 8
    ldg_tiles(0);
    sts_tiles(0);
    __syncthreads();

    for (int i = 0; i < NK; i++) {
        if (i + 1 < NK) ldg_tiles((i + 1) * 32);
        int st = i & 1;

#pragma unroll
        for (int kk = 0; kk < 32; kk += 16) {
            uint32_t af[2][4];
#pragma unroll
            for (int im = 0; im < 2; im++) {
                uint32_t adr = (uint32_t)__cvta_generic_to_shared(
                    &As[st][warp_m * 32 + im * 16 + (lane & 15)][kk + ((lane >> 4) << 3)]);
                asm volatile("ldmatrix.sync.aligned.m8n8.x4.shared.b16 {%0,%1,%2,%3}, [%4];"
                             : "=r"(af[im][0]), "=r"(af[im][1]), "=r"(af[im][2]), "=r"(af[im][3])
                             : "r"(adr));
            }
#pragma unroll
            for (int jn = 0; jn < 8; jn++) {
                int nb = warp_n * 64 + jn * 8;
                uint32_t bf[2];
                uint32_t adr_b = (uint32_t)__cvta_generic_to_shared(
                    &Bs[st][nb + (lane & 7)][kk + (((lane >> 3) & 1) << 3)]);
                asm volatile("ldmatrix.sync.aligned.m8n8.x2.shared.b16 {%0,%1}, [%2];"
                             : "=r"(bf[0]), "=r"(bf[1]) : "r"(adr_b));
#pragma unroll
                for (int im = 0; im < 2; im++) {
                    float* c = acc[im][jn];
                    asm volatile(
                        "mma.sync.aligned.m16n8k16.row.col.f32.f16.f16.f32 "
                        "{%0,%1,%2,%3}, {%4,%5,%6,%7}, {%8,%9}, {%0,%1,%2,%3};"
                        : "+f"(c[0]), "+f"(c[1]), "+f"(c[2]), "+f"(c[3])
                        : "r"(af[im][0]), "r"(af[im][1]), "r"(af[im][2]), "r"(af[im][3]),
                          "r"(bf[0]), "r"(bf[1]));
                }
            }
        }

        if (i + 1 < NK) sts_tiles((i + 1) & 1);  // writes other buffer; its readers
                                                 // finished before last iter's sync
        __syncthreads();
    }

    // ---- epilogue: store feat (fp16), compute el/er per (row, head) ----
    int quad = lane >> 2, tc = lane & 3;
    float pel[2][2][2], per[2][2][2];   // [im][rowhalf][headhalf]
#pragma unroll
    for (int im = 0; im < 2; im++)
#pragma unroll
        for (int rh = 0; rh < 2; rh++)
#pragma unroll
            for (int hh = 0; hh < 2; hh++) { pel[im][rh][hh] = 0.f; per[im][rh][hh] = 0.f; }

#pragma unroll
    for (int im = 0; im < 2; im++) {
        int rowA = row0 + warp_m * 32 + im * 16 + quad;
#pragma unroll
        for (int jn = 0; jn < 8; jn++) {
            int col = warp_n * 64 + jn * 8 + tc * 2;
            int hh = jn >> 2;
            float* c = acc[im][jn];
            float a0 = attn_l[col], a1 = attn_l[col + 1];
            float b0 = attn_r[col], b1 = attn_r[col + 1];
            pel[im][0][hh] += c[0] * a0 + c[1] * a1;
            per[im][0][hh] += c[0] * b0 + c[1] * b1;
            pel[im][1][hh] += c[2] * a0 + c[3] * a1;
            per[im][1][hh] += c[2] * b0 + c[3] * b1;
            if (rowA < NN)
                *reinterpret_cast<__half2*>(&g_feat_h[(size_t)rowA * HC + col]) =
                    __floats2half2_rn(c[0], c[1]);
            if (rowA + 8 < NN)
                *reinterpret_cast<__half2*>(&g_feat_h[(size_t)(rowA + 8) * HC + col]) =
                    __floats2half2_rn(c[2], c[3]);
        }
    }
#pragma unroll
    for (int im = 0; im < 2; im++)
#pragma unroll
        for (int rh = 0; rh < 2; rh++)
#pragma unroll
            for (int hh = 0; hh < 2; hh++) {
                float e = pel[im][rh][hh], r = per[im][rh][hh];
                e += __shfl_xor_sync(0xffffffffu, e, 1);
                e += __shfl_xor_sync(0xffffffffu, e, 2);
                r += __shfl_xor_sync(0xffffffffu, r, 1);
                r += __shfl_xor_sync(0xffffffffu, r, 2);
                if (tc == 0) {
                    int row = row0 + warp_m * 32 + im * 16 + quad + rh * 8;
                    int head = warp_n * 2 + hh;
                    if (row < NN) {
                        g_el[row * HH + head] = e;
                        g_er[row * HH + head] = r;
                    }
                }
            }
}

// ---------------- CSR build (4 edges per thread) ----------------
__global__ void histo_kernel(const int* __restrict__ dst) {
    int i = blockIdx.x * blockDim.x + threadIdx.x;
    if (i >= EE / 4) return;
    int4 d = reinterpret_cast<const int4*>(dst)[i];
    atomicAdd(&g_deg[d.x], 1);
    atomicAdd(&g_deg[d.y], 1);
    atomicAdd(&g_deg[d.z], 1);
    atomicAdd(&g_deg[d.w], 1);
}

// per-block exclusive scan; writes RAW block totals to g_blocksums
__global__ __launch_bounds__(1024) void scan1_kernel() {
    __shared__ int sh[1024];
    int i = blockIdx.x * 1024 + threadIdx.x;
    int v = (i < NN) ? g_deg[i] : 0;
    sh[threadIdx.x] = v;
    __syncthreads();
#pragma unroll
    for (int off = 1; off < 1024; off <<= 1) {
        int t = (threadIdx.x >= off) ? sh[threadIdx.x - off] : 0;
        __syncthreads();
        sh[threadIdx.x] += t;
        __syncthreads();
    }
    if (i < NN) g_rowoff[i] = sh[threadIdx.x] - v;        // exclusive within block
    if (threadIdx.x == 1023) g_blocksums[blockIdx.x] = sh[1023];   // raw total
}

// adds block offsets; each block redundantly scans the 98 totals in smem
// (folds the old scan2 kernel into this one -> one fewer launch)
__global__ __launch_bounds__(1024) void scan3_kernel() {
    __shared__ int shbs[128];
    if (threadIdx.x < 128)
        shbs[threadIdx.x] = (threadIdx.x < NB) ? g_blocksums[threadIdx.x] : 0;
    __syncthreads();
    if (threadIdx.x < 128) {
#pragma unroll
        for (int off = 1; off < 128; off <<= 1) {
            int t = (threadIdx.x >= off) ? shbs[threadIdx.x - off] : 0;
            __syncthreads();
            shbs[threadIdx.x] += t;
            __syncthreads();
        }
    } else {
#pragma unroll
        for (int off = 1; off < 128; off <<= 1) { __syncthreads(); __syncthreads(); }
    }
    int boff = (blockIdx.x > 0) ? shbs[blockIdx.x - 1] : 0;   // exclusive
    int i = blockIdx.x * 1024 + threadIdx.x;
    if (i < NN) {
        int v = g_rowoff[i] + boff;
        g_rowoff[i] = v;
        g_cursor[i] = v;
    }
    if (i == 0) g_rowoff[NN] = EE;
}

__global__ void scatter_kernel(const int* __restrict__ src,
                               const int* __restrict__ dst) {
    int i = blockIdx.x * blockDim.x + threadIdx.x;
    if (i >= EE / 4) return;
    int4 s4 = reinterpret_cast<const int4*>(src)[i];
    int4 d4 = reinterpret_cast<const int4*>(dst)[i];
    int p;
    p = atomicAdd(&g_cursor[d4.x], 1); g_srcsorted[p] = s4.x;
    p = atomicAdd(&g_cursor[d4.y], 1); g_srcsorted[p] = s4.y;
    p = atomicAdd(&g_cursor[d4.z], 1); g_srcsorted[p] = s4.z;
    p = atomicAdd(&g_cursor[d4.w], 1); g_srcsorted[p] = s4.w;
}

// ------- fused single-pass softmax-aggregate + head-mean + relu -------
// Gather loop unrolled x4: 4 independent feat-row loads in flight (MLP).
__global__ __launch_bounds__(256) void aggregate_fused_kernel(
    const float* __restrict__ bias, float* __restrict__ out)
{
    __shared__ float sh_ex[8][32][4];   // [warp][edge-in-chunk][head]
    int wslot = threadIdx.x >> 5;
    int warp = (blockIdx.x * blockDim.x + threadIdx.x) >> 5;
    int lane = threadIdx.x & 31;
    if (warp >= NN) return;
    int n = warp;
    int head = lane >> 3;

    int start = g_rowoff[n];
    int end   = g_rowoff[n + 1];

    float4 er4 = *reinterpret_cast<const float4*>(&g_er[n * HH]);

    float4 den = make_float4(0.f, 0.f, 0.f, 0.f);
    float4 acc = make_float4(0.f, 0.f, 0.f, 0.f);
    const uint2* feat2 = reinterpret_cast<const uint2*>(g_feat_h);

    for (int j0 = start; j0 < end; j0 += 32) {
        int jj = j0 + lane;
        int sj = 0;
        float4 ex4 = make_float4(0.f, 0.f, 0.f, 0.f);
        if (jj < end) {
            sj = g_srcsorted[jj];
            float4 el4 = *reinterpret_cast<const float4*>(&g_el[sj * HH]);
            float v0 = el4.x + er4.x, v1 = el4.y + er4.y;
            float v2 = el4.z + er4.z, v3 = el4.w + er4.w;
            v0 = v0 > 0.f ? v0 : 0.2f * v0;
            v1 = v1 > 0.f ? v1 : 0.2f * v1;
            v2 = v2 > 0.f ? v2 : 0.2f * v2;
            v3 = v3 > 0.f ? v3 : 0.2f * v3;
            ex4 = make_float4(__expf(v0), __expf(v1), __expf(v2), __expf(v3));
            den.x += ex4.x; den.y += ex4.y; den.z += ex4.z; den.w += ex4.w;
        }
        *reinterpret_cast<float4*>(&sh_ex[wslot][lane][0]) = ex4;
        __syncwarp();
        int m = end - j0; if (m > 32) m = 32;
        int t = 0;
        for (; t + 4 <= m; t += 4) {
            int s0 = __shfl_sync(0xffffffffu, sj, t);
            int s1 = __shfl_sync(0xffffffffu, sj, t + 1);
            int s2 = __shfl_sync(0xffffffffu, sj, t + 2);
            int s3 = __shfl_sync(0xffffffffu, sj, t + 3);
            uint2 u0 = feat2[(size_t)s0 * 32 + lane];
            uint2 u1 = feat2[(size_t)s1 * 32 + lane];
            uint2 u2 = feat2[(size_t)s2 * 32 + lane];
            uint2 u3 = feat2[(size_t)s3 * 32 + lane];
            float n0 = sh_ex[wslot][t][head];
            float n1 = sh_ex[wslot][t + 1][head];
            float n2 = sh_ex[wslot][t + 2][head];
            float n3 = sh_ex[wslot][t + 3][head];
            float2 a, b;
            a = __half22float2(*reinterpret_cast<__half2*>(&u0.x));
            b = __half22float2(*reinterpret_cast<__half2*>(&u0.y));
            acc.x += n0 * a.x; acc.y += n0 * a.y; acc.z += n0 * b.x; acc.w += n0 * b.y;
            a = __half22float2(*reinterpret_cast<__half2*>(&u1.x));
            b = __half22float2(*reinterpret_cast<__half2*>(&u1.y));
            acc.x += n1 * a.x; acc.y += n1 * a.y; acc.z += n1 * b.x; acc.w += n1 * b.y;
            a = __half22float2(*reinterpret_cast<__half2*>(&u2.x));
            b = __half22float2(*reinterpret_cast<__half2*>(&u2.y));
            acc.x += n2 * a.x; acc.y += n2 * a.y; acc.z += n2 * b.x; acc.w += n2 * b.y;
            a = __half22float2(*reinterpret_cast<__half2*>(&u3.x));
            b = __half22float2(*reinterpret_cast<__half2*>(&u3.y));
            acc.x += n3 * a.x; acc.y += n3 * a.y; acc.z += n3 * b.x; acc.w += n3 * b.y;
        }
        for (; t < m; t++) {
            int s = __shfl_sync(0xffffffffu, sj, t);
            float num = sh_ex[wslot][t][head];
            uint2 u = feat2[(size_t)s * 32 + lane];
            float2 f01 = __half22float2(*reinterpret_cast<__half2*>(&u.x));
            float2 f23 = __half22float2(*reinterpret_cast<__half2*>(&u.y));
            acc.x += num * f01.x; acc.y += num * f01.y;
            acc.z += num * f23.x; acc.w += num * f23.y;
        }
        __syncwarp();
    }

#pragma unroll
    for (int off = 16; off > 0; off >>= 1) {
        den.x += __shfl_xor_sync(0xffffffffu, den.x, off);
        den.y += __shfl_xor_sync(0xffffffffu, den.y, off);
        den.z += __shfl_xor_sync(0xffffffffu, den.z, off);
        den.w += __shfl_xor_sync(0xffffffffu, den.w, off);
    }
    float dmine = (head == 0) ? den.x : (head == 1) ? den.y
                 : (head == 2) ? den.z : den.w;
    float rinv = (dmine > 0.f) ? __fdividef(1.f, dmine) : 0.f;
    acc.x *= rinv; acc.y *= rinv; acc.z *= rinv; acc.w *= rinv;

#pragma unroll
    for (int off = 8; off <= 16; off <<= 1) {
        acc.x += __shfl_xor_sync(0xffffffffu, acc.x, off);
        acc.y += __shfl_xor_sync(0xffffffffu, acc.y, off);
        acc.z += __shfl_xor_sync(0xffffffffu, acc.z, off);
        acc.w += __shfl_xor_sync(0xffffffffu, acc.w, off);
    }
    if (lane < 8) {
        float bs[4] = {0.f, 0.f, 0.f, 0.f};
#pragma unroll
        for (int h = 0; h < HH; h++) {
#pragma unroll
            for (int k = 0; k < 4; k++) bs[k] += bias[h * CC + lane * 4 + k];
        }
        float4 o;
        o.x = fmaxf(0.25f * (acc.x + bs[0]), 0.f);
        o.y = fmaxf(0.25f * (acc.y + bs[1]), 0.f);
        o.z = fmaxf(0.25f * (acc.z + bs[2]), 0.f);
        o.w = fmaxf(0.25f * (acc.w + bs[3]), 0.f);
        reinterpret_cast<float4*>(out)[n * 8 + lane] = o;
    }
}

// ---------------- launch: single stream, serial chain ----------------
extern "C" void kernel_launch(void* const* d_in, const int* in_sizes, int n_in,
                              void* d_out, int out_size)
{
    const float* x      = (const float*)d_in[0];
    const int*   src    = (const int*)d_in[1];
    const int*   dst    = (const int*)d_in[2];
    const float* W      = (const float*)d_in[3];
    const float* attn_l = (const float*)d_in[4];
    const float* attn_r = (const float*)d_in[5];
    const float* bias   = (const float*)d_in[6];
    float* out = (float*)d_out;

    prep_kernel<<<(NN + 255) / 256, 256>>>(W);
    gemm_feat_tc_kernel<<<(NN + 127) / 128, 256>>>(x, attn_l, attn_r);

    histo_kernel<<<(EE / 4 + 255) / 256, 256>>>(dst);
    scan1_kernel<<<NB, 1024>>>();
    scan3_kernel<<<NB, 1024>>>();
    scatter_kernel<<<(EE / 4 + 255) / 256, 256>>>(src, dst);

    aggregate_fused_kernel<<<(NN * 32 + 255) / 256, 256>>>(bias, out);
}

// round 16
// speedup vs baseline: 1.5637x; 1.0398x over previous
#include <cstdint>
#include <cuda_runtime.h>
#include <cuda_fp16.h>
#include <cuda_bf16.h>

#define NN 100000
#define EE 1600000
#define IN_F 256
#define HH 4
#define CC 32
#define HC 128           // HH*CC
#define NB 98            // ceil(NN/1024) scan blocks
#define AST 40           // smem stride in half (80B rows: conflict-free ldmatrix)

// ---------------- device scratch (no allocations allowed) ----------------
__device__ __half g_feat_h[NN * HC];  // projected features [N, H*C] (fp16)
__device__ float g_el[NN * HH];       // left attention logits  [N,H]
__device__ float g_er[NN * HH];       // right attention logits [N,H]
__device__ int   g_deg[NN];           // in-degree histogram (self-reset each run)
__device__ int   g_rowoff[NN + 1];    // CSR row offsets (by dst)
__device__ int   g_cursor[NN];        // scatter cursors
__device__ int   g_bs_flagged[128];   // lookback: block total+1 (0 = not ready)
__device__ int   g_srcsorted[EE];     // src node id per edge, grouped by dst
__device__ __half g_Wt[HC * IN_F];    // W^T fp16: [n=128][k=256]

// ------- kernel 0: W -> W^T fp16 -------
__global__ void prep_kernel(const float* __restrict__ W) {
    int i = blockIdx.x * blockDim.x + threadIdx.x;
    if (i < IN_F * HC) {
        int k = i >> 7, n = i & 127;
        g_Wt[n * IN_F + k] = __float2half_rn(W[i]);
    }
}

// ---------------- kernel 1: feat = x @ W via fp16 tensor cores ----------
// 128x128 out tile, 8 warps (4m x 2n), warp tile 32x64.
// 2-stage smem double buffer; fused el/er epilogue via quad-shfl reduction.
__global__ __launch_bounds__(256) void gemm_feat_tc_kernel(
    const float* __restrict__ x,
    const float* __restrict__ attn_l, const float* __restrict__ attn_r)
{
    __shared__ __half As[2][128][AST];
    __shared__ __half Bs[2][128][AST];

    int tid = threadIdx.x, lane = tid & 31, wid = tid >> 5;
    int warp_m = wid >> 1;          // 0..3
    int warp_n = wid & 1;           // 0..1
    int row0 = blockIdx.x * 128;

    float acc[2][8][4];
#pragma unroll
    for (int im = 0; im < 2; im++)
#pragma unroll
        for (int jn = 0; jn < 8; jn++)
#pragma unroll
            for (int r = 0; r < 4; r++) acc[im][jn][r] = 0.f;

    float4 av[4];     // staged x tile (fp32, converted at STS)
    uint4  bv[2];     // staged W tile (fp16 packed)

    auto ldg_tiles = [&](int k0) {
#pragma unroll
        for (int l = 0; l < 4; l++) {
            int idx = tid + l * 256;            // 0..1023 float4 slots
            int r = idx >> 3, c4 = (idx & 7) << 2;
            int row = row0 + r;
            av[l] = make_float4(0.f, 0.f, 0.f, 0.f);
            if (row < NN)
                av[l] = *reinterpret_cast<const float4*>(&x[(size_t)row * IN_F + k0 + c4]);
        }
#pragma unroll
        for (int l = 0; l < 2; l++) {
            int s = tid + l * 256;              // 0..511 uint4 slots
            int n = s >> 2, k8 = (s & 3) << 3;
            bv[l] = *reinterpret_cast<const uint4*>(&g_Wt[n * IN_F + k0 + k8]);
        }
    };
    auto sts_tiles = [&](int st) {
#pragma unroll
        for (int l = 0; l < 4; l++) {
            int idx = tid + l * 256;
            int r = idx >> 3, c4 = (idx & 7) << 2;
            *reinterpret_cast<__half2*>(&As[st][r][c4])     = __floats2half2_rn(av[l].x, av[l].y);
            *reinterpret_cast<__half2*>(&As[st][r][c4 + 2]) = __floats2half2_rn(av[l].z, av[l].w);
        }
#pragma unroll
        for (int l = 0; l < 2; l++) {
            int s = tid + l * 256;
            int n = s >> 2, k8 = (s & 3) << 3;
            *reinterpret_cast<uint4*>(&Bs[st][n][k8]) = bv[l];
        }
    };

    const int NK = IN_F / 32;   // 8
    ldg_tiles(0);
    sts_tiles(0);
    __syncthreads();

    for (int i = 0; i < NK; i++) {
        if (i + 1 < NK) ldg_tiles((i + 1) * 32);
        int st = i & 1;

#pragma unroll
        for (int kk = 0; kk < 32; kk += 16) {
            uint32_t af[2][4];
#pragma unroll
            for (int im = 0; im < 2; im++) {
                uint32_t adr = (uint32_t)__cvta_generic_to_shared(
                    &As[st][warp_m * 32 + im * 16 + (lane & 15)][kk + ((lane >> 4) << 3)]);
                asm volatile("ldmatrix.sync.aligned.m8n8.x4.shared.b16 {%0,%1,%2,%3}, [%4];"
                             : "=r"(af[im][0]), "=r"(af[im][1]), "=r"(af[im][2]), "=r"(af[im][3])
                             : "r"(adr));
            }
#pragma unroll
            for (int jn = 0; jn < 8; jn++) {
                int nb = warp_n * 64 + jn * 8;
                uint32_t bf[2];
                uint32_t adr_b = (uint32_t)__cvta_generic_to_shared(
                    &Bs[st][nb + (lane & 7)][kk + (((lane >> 3) & 1) << 3)]);
                asm volatile("ldmatrix.sync.aligned.m8n8.x2.shared.b16 {%0,%1}, [%2];"
                             : "=r"(bf[0]), "=r"(bf[1]) : "r"(adr_b));
#pragma unroll
                for (int im = 0; im < 2; im++) {
                    float* c = acc[im][jn];
                    asm volatile(
                        "mma.sync.aligned.m16n8k16.row.col.f32.f16.f16.f32 "
                        "{%0,%1,%2,%3}, {%4,%5,%6,%7}, {%8,%9}, {%0,%1,%2,%3};"
                        : "+f"(c[0]), "+f"(c[1]), "+f"(c[2]), "+f"(c[3])
                        : "r"(af[im][0]), "r"(af[im][1]), "r"(af[im][2]), "r"(af[im][3]),
                          "r"(bf[0]), "r"(bf[1]));
                }
            }
        }

        if (i + 1 < NK) sts_tiles((i + 1) & 1);
        __syncthreads();
    }

    // ---- epilogue: store feat (fp16), compute el/er per (row, head) ----
    int quad = lane >> 2, tc = lane & 3;
    float pel[2][2][2], per[2][2][2];   // [im][rowhalf][headhalf]
#pragma unroll
    for (int im = 0; im < 2; im++)
#pragma unroll
        for (int rh = 0; rh < 2; rh++)
#pragma unroll
            for (int hh = 0; hh < 2; hh++) { pel[im][rh][hh] = 0.f; per[im][rh][hh] = 0.f; }

#pragma unroll
    for (int im = 0; im < 2; im++) {
        int rowA = row0 + warp_m * 32 + im * 16 + quad;
#pragma unroll
        for (int jn = 0; jn < 8; jn++) {
            int col = warp_n * 64 + jn * 8 + tc * 2;
            int hh = jn >> 2;
            float* c = acc[im][jn];
            float a0 = attn_l[col], a1 = attn_l[col + 1];
            float b0 = attn_r[col], b1 = attn_r[col + 1];
            pel[im][0][hh] += c[0] * a0 + c[1] * a1;
            per[im][0][hh] += c[0] * b0 + c[1] * b1;
            pel[im][1][hh] += c[2] * a0 + c[3] * a1;
            per[im][1][hh] += c[2] * b0 + c[3] * b1;
            if (rowA < NN)
                *reinterpret_cast<__half2*>(&g_feat_h[(size_t)rowA * HC + col]) =
                    __floats2half2_rn(c[0], c[1]);
            if (rowA + 8 < NN)
                *reinterpret_cast<__half2*>(&g_feat_h[(size_t)(rowA + 8) * HC + col]) =
                    __floats2half2_rn(c[2], c[3]);
        }
    }
#pragma unroll
    for (int im = 0; im < 2; im++)
#pragma unroll
        for (int rh = 0; rh < 2; rh++)
#pragma unroll
            for (int hh = 0; hh < 2; hh++) {
                float e = pel[im][rh][hh], r = per[im][rh][hh];
                e += __shfl_xor_sync(0xffffffffu, e, 1);
                e += __shfl_xor_sync(0xffffffffu, e, 2);
                r += __shfl_xor_sync(0xffffffffu, r, 1);
                r += __shfl_xor_sync(0xffffffffu, r, 2);
                if (tc == 0) {
                    int row = row0 + warp_m * 32 + im * 16 + quad + rh * 8;
                    int head = warp_n * 2 + hh;
                    if (row < NN) {
                        g_el[row * HH + head] = e;
                        g_er[row * HH + head] = r;
                    }
                }
            }
}

// ---------------- CSR build (4 edges per thread) ----------------
// Also zeroes the lookback flags consumed by the scan that follows it.
__global__ void histo_kernel(const int* __restrict__ dst) {
    int i = blockIdx.x * blockDim.x + threadIdx.x;
    if (i < 128) g_bs_flagged[i] = 0;
    if (i >= EE / 4) return;
    int4 d = reinterpret_cast<const int4*>(dst)[i];
    atomicAdd(&g_deg[d.x], 1);
    atomicAdd(&g_deg[d.y], 1);
    atomicAdd(&g_deg[d.z], 1);
    atomicAdd(&g_deg[d.w], 1);
}

// single-kernel exclusive scan via decoupled lookback.
// 98 blocks = one wave (all resident) -> spin-free-dom guaranteed.
// Publishes total+1 through atomicExch (value doubles as ready flag).
// Self-resets g_deg to zero for the next graph replay.
__global__ __launch_bounds__(1024) void scan_fused_kernel() {
    __shared__ int sh[1024];
    __shared__ int s_sum;
    int b = blockIdx.x;
    int i = b * 1024 + threadIdx.x;
    int v = (i < NN) ? g_deg[i] : 0;
    if (i < NN) g_deg[i] = 0;                 // reset for next replay
    sh[threadIdx.x] = v;
    __syncthreads();
#pragma unroll
    for (int off = 1; off < 1024; off <<= 1) {
        int t = (threadIdx.x >= off) ? sh[threadIdx.x - off] : 0;
        __syncthreads();
        sh[threadIdx.x] += t;
        __syncthreads();
    }
    if (threadIdx.x == 1023)
        atomicExch(&g_bs_flagged[b], sh[1023] + 1);   // publish total (+1 as flag)
    if (threadIdx.x == 0) s_sum = 0;
    __syncthreads();

    int part = 0;
    if ((int)threadIdx.x < b) {               // b <= 97 < 1024
        volatile int* f = &g_bs_flagged[threadIdx.x];
        int val;
        do { val = *f; } while (val == 0);
        part = val - 1;
    }
#pragma unroll
    for (int off = 16; off > 0; off >>= 1)
        part += __shfl_down_sync(0xffffffffu, part, off);
    if ((threadIdx.x & 31) == 0 && part != 0) atomicAdd(&s_sum, part);
    __syncthreads();

    int excl = s_sum + sh[threadIdx.x] - v;   // exclusive global prefix
    if (i < NN) { g_rowoff[i] = excl; g_cursor[i] = excl; }
    if (i == 0) g_rowoff[NN] = EE;
}

__global__ void scatter_kernel(const int* __restrict__ src,
                               const int* __restrict__ dst) {
    int i = blockIdx.x * blockDim.x + threadIdx.x;
    if (i >= EE / 4) return;
    int4 s4 = reinterpret_cast<const int4*>(src)[i];
    int4 d4 = reinterpret_cast<const int4*>(dst)[i];
    int p;
    p = atomicAdd(&g_cursor[d4.x], 1); g_srcsorted[p] = s4.x;
    p = atomicAdd(&g_cursor[d4.y], 1); g_srcsorted[p] = s4.y;
    p = atomicAdd(&g_cursor[d4.z], 1); g_srcsorted[p] = s4.z;
    p = atomicAdd(&g_cursor[d4.w], 1); g_srcsorted[p] = s4.w;
}

// ------- fused single-pass softmax-aggregate + head-mean + relu -------
__global__ __launch_bounds__(256) void aggregate_fused_kernel(
    const float* __restrict__ bias, float* __restrict__ out)
{
    __shared__ float sh_ex[8][32][4];   // [warp][edge-in-chunk][head]
    int wslot = threadIdx.x >> 5;
    int warp = (blockIdx.x * blockDim.x + threadIdx.x) >> 5;
    int lane = threadIdx.x & 31;
    if (warp >= NN) return;
    int n = warp;
    int head = lane >> 3;

    int start = g_rowoff[n];
    int end   = g_rowoff[n + 1];

    float4 er4 = *reinterpret_cast<const float4*>(&g_er[n * HH]);

    float4 den = make_float4(0.f, 0.f, 0.f, 0.f);
    float4 acc = make_float4(0.f, 0.f, 0.f, 0.f);
    const uint2* feat2 = reinterpret_cast<const uint2*>(g_feat_h);

    for (int j0 = start; j0 < end; j0 += 32) {
        int jj = j0 + lane;
        int sj = 0;
        float4 ex4 = make_float4(0.f, 0.f, 0.f, 0.f);
        if (jj < end) {
            sj = g_srcsorted[jj];
            float4 el4 = *reinterpret_cast<const float4*>(&g_el[sj * HH]);
            float v0 = el4.x + er4.x, v1 = el4.y + er4.y;
            float v2 = el4.z + er4.z, v3 = el4.w + er4.w;
            v0 = v0 > 0.f ? v0 : 0.2f * v0;
            v1 = v1 > 0.f ? v1 : 0.2f * v1;
            v2 = v2 > 0.f ? v2 : 0.2f * v2;
            v3 = v3 > 0.f ? v3 : 0.2f * v3;
            ex4 = make_float4(__expf(v0), __expf(v1), __expf(v2), __expf(v3));
            den.x += ex4.x; den.y += ex4.y; den.z += ex4.z; den.w += ex4.w;
        }
        *reinterpret_cast<float4*>(&sh_ex[wslot][lane][0]) = ex4;
        __syncwarp();
        int m = end - j0; if (m > 32) m = 32;
        int t = 0;
        for (; t + 4 <= m; t += 4) {
            int s0 = __shfl_sync(0xffffffffu, sj, t);
            int s1 = __shfl_sync(0xffffffffu, sj, t + 1);
            int s2 = __shfl_sync(0xffffffffu, sj, t + 2);
            int s3 = __shfl_sync(0xffffffffu, sj, t + 3);
            uint2 u0 = feat2[(size_t)s0 * 32 + lane];
            uint2 u1 = feat2[(size_t)s1 * 32 + lane];
            uint2 u2 = feat2[(size_t)s2 * 32 + lane];
            uint2 u3 = feat2[(size_t)s3 * 32 + lane];
            float n0 = sh_ex[wslot][t][head];
            float n1 = sh_ex[wslot][t + 1][head];
            float n2 = sh_ex[wslot][t + 2][head];
            float n3 = sh_ex[wslot][t + 3][head];
            float2 a, b;
            a = __half22float2(*reinterpret_cast<__half2*>(&u0.x));
            b = __half22float2(*reinterpret_cast<__half2*>(&u0.y));
            acc.x += n0 * a.x; acc.y += n0 * a.y; acc.z += n0 * b.x; acc.w += n0 * b.y;
            a = __half22float2(*reinterpret_cast<__half2*>(&u1.x));
            b = __half22float2(*reinterpret_cast<__half2*>(&u1.y));
            acc.x += n1 * a.x; acc.y += n1 * a.y; acc.z += n1 * b.x; acc.w += n1 * b.y;
            a = __half22float2(*reinterpret_cast<__half2*>(&u2.x));
            b = __half22float2(*reinterpret_cast<__half2*>(&u2.y));
            acc.x += n2 * a.x; acc.y += n2 * a.y; acc.z += n2 * b.x; acc.w += n2 * b.y;
            a = __half22float2(*reinterpret_cast<__half2*>(&u3.x));
            b = __half22float2(*reinterpret_cast<__half2*>(&u3.y));
            acc.x += n3 * a.x; acc.y += n3 * a.y; acc.z += n3 * b.x; acc.w += n3 * b.y;
        }
        for (; t < m; t++) {
            int s = __shfl_sync(0xffffffffu, sj, t);
            float num = sh_ex[wslot][t][head];
            uint2 u = feat2[(size_t)s * 32 + lane];
            float2 f01 = __half22float2(*reinterpret_cast<__half2*>(&u.x));
            float2 f23 = __half22float2(*reinterpret_cast<__half2*>(&u.y));
            acc.x += num * f01.x; acc.y += num * f01.y;
            acc.z += num * f23.x; acc.w += num * f23.y;
        }
        __syncwarp();
    }

#pragma unroll
    for (int off = 16; off > 0; off >>= 1) {
        den.x += __shfl_xor_sync(0xffffffffu, den.x, off);
        den.y += __shfl_xor_sync(0xffffffffu, den.y, off);
        den.z += __shfl_xor_sync(0xffffffffu, den.z, off);
        den.w += __shfl_xor_sync(0xffffffffu, den.w, off);
    }
    float dmine = (head == 0) ? den.x : (head == 1) ? den.y
                 : (head == 2) ? den.z : den.w;
    float rinv = (dmine > 0.f) ? __fdividef(1.f, dmine) : 0.f;
    acc.x *= rinv; acc.y *= rinv; acc.z *= rinv; acc.w *= rinv;

#pragma unroll
    for (int off = 8; off <= 16; off <<= 1) {
        acc.x += __shfl_xor_sync(0xffffffffu, acc.x, off);
        acc.y += __shfl_xor_sync(0xffffffffu, acc.y, off);
        acc.z += __shfl_xor_sync(0xffffffffu, acc.z, off);
        acc.w += __shfl_xor_sync(0xffffffffu, acc.w, off);
    }
    if (lane < 8) {
        float bs[4] = {0.f, 0.f, 0.f, 0.f};
#pragma unroll
        for (int h = 0; h < HH; h++) {
#pragma unroll
            for (int k = 0; k < 4; k++) bs[k] += bias[h * CC + lane * 4 + k];
        }
        float4 o;
        o.x = fmaxf(0.25f * (acc.x + bs[0]), 0.f);
        o.y = fmaxf(0.25f * (acc.y + bs[1]), 0.f);
        o.z = fmaxf(0.25f * (acc.z + bs[2]), 0.f);
        o.w = fmaxf(0.25f * (acc.w + bs[3]), 0.f);
        reinterpret_cast<float4*>(out)[n * 8 + lane] = o;
    }
}

// ---------------- launch: CSR chain forked beside GEMM chain ----------------
extern "C" void kernel_launch(void* const* d_in, const int* in_sizes, int n_in,
                              void* d_out, int out_size)
{
    const float* x      = (const float*)d_in[0];
    const int*   src    = (const int*)d_in[1];
    const int*   dst    = (const int*)d_in[2];
    const float* W      = (const float*)d_in[3];
    const float* attn_l = (const float*)d_in[4];
    const float* attn_r = (const float*)d_in[5];
    const float* bias   = (const float*)d_in[6];
    float* out = (float*)d_out;

    static cudaStream_t s2 = nullptr;
    static cudaEvent_t evFork = nullptr, evJoin = nullptr;
    static bool ok2 = false;
    if (!evFork) {
        ok2 = (cudaStreamCreateWithFlags(&s2, cudaStreamNonBlocking) == cudaSuccess);
        cudaEventCreateWithFlags(&evFork, cudaEventDisableTiming);
        cudaEventCreateWithFlags(&evJoin, cudaEventDisableTiming);
    }
    cudaStream_t sb = ok2 ? s2 : (cudaStream_t)0;

    if (ok2) {
        cudaEventRecord(evFork, 0);
        cudaStreamWaitEvent(s2, evFork, 0);
    }

    // CSR chain (side stream): histo -> fused scan -> scatter
    histo_kernel<<<(EE / 4 + 255) / 256, 256, 0, sb>>>(dst);
    scan_fused_kernel<<<NB, 1024, 0, sb>>>();
    scatter_kernel<<<(EE / 4 + 255) / 256, 256, 0, sb>>>(src, dst);

    // GEMM chain (main stream)
    prep_kernel<<<(IN_F * HC + 255) / 256, 256>>>(W);
    gemm_feat_tc_kernel<<<(NN + 127) / 128, 256>>>(x, attn_l, attn_r);

    if (ok2) {
        cudaEventRecord(evJoin, s2);
        cudaStreamWaitEvent(0, evJoin, 0);
    }

    aggregate_fused_kernel<<<(NN * 32 + 255) / 256, 256>>>(bias, out);
}